// round 1
// baseline (speedup 1.0000x reference)
#include <cuda_runtime.h>

#define B    2048
#define IN   256
#define H    128
#define OUTD 128
#define RANK 8
#define EPS  1e-5f

// bilinear GEMM tiling
#define BM      64          // batch rows per CTA
#define BMP     68          // padded smem row (bank stagger, keeps 16B align)
#define PSPLIT  8           // p-dimension split across CTA groups
#define PP      (H/PSPLIT)  // 16 p values per split
#define QC      16          // q rows per smem chunk
#define NCH     (PP*(H/QC)) // 128 chunks per CTA

// ---------------- scratch (device globals; no allocation) ----------------
__device__ float g_Z[B*H];               // relu(X@W1+b1), fixed across ranks
__device__ float g_Zi[B*H];              // current carry (normalized)
__device__ float g_part[PSPLIT][B*H];    // per-split partial bilinear sums
__device__ float g_raw[B*H];             // combined raw bilinear output
__device__ float g_Y[B*H];               // running Y accumulator
__device__ float g_mean[H];
__device__ float g_rstd[H];

// ---------------- Z = relu(X@W1 + b1); Zi = Z ----------------
__global__ void k_z(const float* __restrict__ X, const float* __restrict__ W1,
                    const float* __restrict__ b1) {
    __shared__ float Xs[8][IN];
    int b0 = blockIdx.x * 8;
    int t  = threadIdx.x;   // 128 threads, one output feature each
    for (int i = t; i < 8*IN; i += 128)
        Xs[i/IN][i%IN] = X[(b0 + i/IN)*IN + (i%IN)];
    __syncthreads();
    float acc[8];
    float bias = b1[t];
#pragma unroll
    for (int i = 0; i < 8; i++) acc[i] = bias;
    for (int j = 0; j < IN; j++) {
        float w = W1[j*H + t];
#pragma unroll
        for (int i = 0; i < 8; i++) acc[i] += Xs[i][j] * w;
    }
#pragma unroll
    for (int i = 0; i < 8; i++) {
        float z = fmaxf(acc[i], 0.0f);
        g_Z [(b0+i)*H + t] = z;
        g_Zi[(b0+i)*H + t] = z;
    }
}

// ---------------- raw_r[b,k] = sum_{p,q} Zi[b,p] * P_r[p,q,k] * Z[b,q] ----------------
// grid: (B/BM, PSPLIT), block: 256. Each CTA handles 64 b-rows, 16 p-values,
// all q (128) and all k (128). Writes its partial to g_part[blockIdx.y].
__global__ __launch_bounds__(256) void k_bilinear(const float* __restrict__ Pr) {
    __shared__ __align__(16) float Zs [H][BMP];   // Z  transposed tile  (q-major)
    __shared__ __align__(16) float Zis[PP][BMP];  // Zi transposed tile  (p-major)
    __shared__ __align__(16) float Ps [2][QC][H]; // double-buffered P chunk

    int tid = threadIdx.x;
    int b0  = blockIdx.x * BM;
    int p0  = blockIdx.y * PP;

    // load Z tile (transpose: Zs[q][b])
    for (int i = tid; i < BM*H; i += 256) {
        int bb = i >> 7, q = i & 127;          // global read coalesced along q
        Zs[q][bb] = g_Z[(b0+bb)*H + q];
    }
    // load Zi tile (transpose: Zis[p][b]) for this p-split
    for (int i = tid; i < BM*PP; i += 256) {
        int bb = i >> 4, p = i & 15;
        Zis[p][bb] = g_Zi[(b0+bb)*H + p0 + p];
    }
    __syncthreads();

    int tc  = tid & 15, tr = tid >> 4;
    int kb  = tc * 8;       // 8 k-cols per thread
    int bb4 = tr * 4;       // 4 b-rows per thread

    float acc[4][8];
#pragma unroll
    for (int i = 0; i < 4; i++)
#pragma unroll
        for (int j = 0; j < 8; j++) acc[i][j] = 0.0f;

    // P chunks are fully contiguous: chunk ch covers floats [ch*2048, (ch+1)*2048)
    // of the p0 slice (p = ch/8 local, q0 = (ch%8)*16, all k).
    const float4* Psrc = reinterpret_cast<const float4*>(Pr + (size_t)p0 * H * H);
    float4 pr0 = Psrc[tid];
    float4 pr1 = Psrc[tid + 256];

    int buf = 0;
    for (int ch = 0; ch < NCH; ch++) {
        float4* dst = reinterpret_cast<float4*>(&Ps[buf][0][0]);
        dst[tid]       = pr0;
        dst[tid + 256] = pr1;
        __syncthreads();
        if (ch + 1 < NCH) {
            const float4* nxt = Psrc + (size_t)(ch + 1) * 512;
            pr0 = nxt[tid];
            pr1 = nxt[tid + 256];
        }
        int p  = ch >> 3;
        int q0 = (ch & 7) * QC;
        float zi0 = Zis[p][bb4+0], zi1 = Zis[p][bb4+1];
        float zi2 = Zis[p][bb4+2], zi3 = Zis[p][bb4+3];
#pragma unroll
        for (int q = 0; q < QC; q++) {
            float4 zq = *reinterpret_cast<const float4*>(&Zs[q0+q][bb4]);
            float av[4];
            av[0] = zi0 * zq.x; av[1] = zi1 * zq.y;
            av[2] = zi2 * zq.z; av[3] = zi3 * zq.w;
            float4 u = *reinterpret_cast<const float4*>(&Ps[buf][q][kb]);
            float4 v = *reinterpret_cast<const float4*>(&Ps[buf][q][kb+4]);
            float pv[8] = {u.x,u.y,u.z,u.w,v.x,v.y,v.z,v.w};
#pragma unroll
            for (int i = 0; i < 4; i++)
#pragma unroll
                for (int j = 0; j < 8; j++)
                    acc[i][j] += av[i] * pv[j];
        }
        buf ^= 1;
    }

    float* outp = g_part[blockIdx.y];
#pragma unroll
    for (int i = 0; i < 4; i++) {
        float4 w0 = make_float4(acc[i][0], acc[i][1], acc[i][2], acc[i][3]);
        float4 w1 = make_float4(acc[i][4], acc[i][5], acc[i][6], acc[i][7]);
        float4* o = reinterpret_cast<float4*>(&outp[(size_t)(b0+bb4+i)*H + kb]);
        o[0] = w0;
        o[1] = w1;
    }
}

// ---------------- combine p-splits + per-feature batch stats ----------------
// grid: H CTAs (one feature each), block 256
__global__ void k_stats_combine() {
    int k = blockIdx.x;
    int t = threadIdx.x;
    float s = 0.0f, s2 = 0.0f;
    for (int b = t; b < B; b += 256) {
        float v = 0.0f;
#pragma unroll
        for (int sp = 0; sp < PSPLIT; sp++) v += g_part[sp][b*H + k];
        g_raw[b*H + k] = v;
        s  += v;
        s2 += v*v;
    }
    __shared__ float ss[256], ss2[256];
    ss[t] = s; ss2[t] = s2;
    __syncthreads();
    for (int o = 128; o > 0; o >>= 1) {
        if (t < o) { ss[t] += ss[t+o]; ss2[t] += ss2[t+o]; }
        __syncthreads();
    }
    if (t == 0) {
        float m   = ss[0]  * (1.0f/B);
        float var = ss2[0] * (1.0f/B) - m*m;
        g_mean[k] = m;
        g_rstd[k] = rsqrtf(var + EPS);
    }
}

// ---------------- stats of Y (final BN) ----------------
__global__ void k_stats_y() {
    int k = blockIdx.x;
    int t = threadIdx.x;
    float s = 0.0f, s2 = 0.0f;
    for (int b = t; b < B; b += 256) {
        float v = g_Y[b*H + k];
        s += v; s2 += v*v;
    }
    __shared__ float ss[256], ss2[256];
    ss[t] = s; ss2[t] = s2;
    __syncthreads();
    for (int o = 128; o > 0; o >>= 1) {
        if (t < o) { ss[t] += ss[t+o]; ss2[t] += ss2[t+o]; }
        __syncthreads();
    }
    if (t == 0) {
        float m   = ss[0]  * (1.0f/B);
        float var = ss2[0] * (1.0f/B) - m*m;
        g_mean[k] = m;
        g_rstd[k] = rsqrtf(var + EPS);
    }
}

// ---------------- normalize + Y accumulate ----------------
// grid: B*H/256, block 256
__global__ void k_norm(const float* __restrict__ gz, const float* __restrict__ bz,
                       int first) {
    int idx = blockIdx.x * 256 + threadIdx.x;
    int k = idx & (H-1);
    float zi = (g_raw[idx] - g_mean[k]) * g_rstd[k] * gz[k] + bz[k];
    g_Zi[idx] = zi;
    float yc = zi * (1.0f/RANK);
    g_Y[idx] = first ? yc : (g_Y[idx] + yc);
}

// ---------------- out = relu(relu(BN(Y)@W3+b3) + relu(X@W2+b2)) ----------------
__global__ void k_final(const float* __restrict__ X,  const float* __restrict__ W2,
                        const float* __restrict__ b2, const float* __restrict__ W3,
                        const float* __restrict__ b3, const float* __restrict__ gy,
                        const float* __restrict__ by, float* __restrict__ out) {
    __shared__ float Xs[8][IN];
    __shared__ float Ys[8][H];
    int b0 = blockIdx.x * 8;
    int t  = threadIdx.x;   // 128 threads
    for (int i = t; i < 8*IN; i += 128)
        Xs[i/IN][i%IN] = X[(b0 + i/IN)*IN + (i%IN)];
    float m = g_mean[t], rs = g_rstd[t], g = gy[t], bb = by[t];
#pragma unroll
    for (int i = 0; i < 8; i++) {
        float y = g_Y[(b0+i)*H + t];
        Ys[i][t] = (y - m) * rs * g + bb;
    }
    __syncthreads();
    float s1[8], s2[8];
    float bv3 = b3[t], bv2 = b2[t];
#pragma unroll
    for (int i = 0; i < 8; i++) { s1[i] = bv3; s2[i] = bv2; }
    for (int h = 0; h < H; h++) {
        float w = W3[h*OUTD + t];
#pragma unroll
        for (int i = 0; i < 8; i++) s1[i] += Ys[i][h] * w;
    }
    for (int j = 0; j < IN; j++) {
        float w = W2[j*OUTD + t];
#pragma unroll
        for (int i = 0; i < 8; i++) s2[i] += Xs[i][j] * w;
    }
#pragma unroll
    for (int i = 0; i < 8; i++) {
        float r = fmaxf(s1[i], 0.0f) + fmaxf(s2[i], 0.0f);
        out[(b0+i)*OUTD + t] = fmaxf(r, 0.0f);
    }
}

// ---------------- launch ----------------
extern "C" void kernel_launch(void* const* d_in, const int* in_sizes, int n_in,
                              void* d_out, int out_size) {
    const float* X  = (const float*)d_in[0];
    const float* W1 = (const float*)d_in[1];
    const float* b1 = (const float*)d_in[2];
    const float* W2 = (const float*)d_in[3];
    const float* b2 = (const float*)d_in[4];
    const float* W3 = (const float*)d_in[5];
    const float* b3 = (const float*)d_in[6];
    const float* P  = (const float*)d_in[7];
    const float* gz = (const float*)d_in[8];
    const float* bz = (const float*)d_in[9];
    const float* gy = (const float*)d_in[10];
    const float* by = (const float*)d_in[11];
    float* out = (float*)d_out;

    k_z<<<B/8, 128>>>(X, W1, b1);
    for (int r = 0; r < RANK; r++) {
        k_bilinear<<<dim3(B/BM, PSPLIT), 256>>>(P + (size_t)r * H * H * H);
        k_stats_combine<<<H, 256>>>();
        k_norm<<<B*H/256, 256>>>(gz, bz, (r == 0) ? 1 : 0);
    }
    k_stats_y<<<H, 256>>>();
    k_final<<<B/8, 128>>>(X, W2, b2, W3, b3, gy, by, out);
}